// round 2
// baseline (speedup 1.0000x reference)
#include <cuda_runtime.h>
#include <cuda_bf16.h>
#include <math.h>

// ---------------------------------------------------------------------------
//  x (1024,4,84,84) -> conv1 5x5 p2 -> pool -> relu : a1 (1024,32,42,42)
//  conv2 5x5 p1 -> pool -> relu : a2 (1024,32,20,20)
//  conv3 4x4 p1 -> pool -> relu : a3 (1024,64,9,9)
//  conv4 3x3 p1 -> pool -> relu -> flatten : feat (1024,1024)
//  LSTM T=16 B=64 H=512 ; heads -> out (1024,19) + hT + cT
// ---------------------------------------------------------------------------

#define NSAMP 1024

__device__ float g_a1[NSAMP * 32 * 42 * 42];
__device__ float g_a2[NSAMP * 32 * 20 * 20];
__device__ float g_a3[NSAMP * 64 * 9 * 9];
__device__ float g_feat[NSAMP * 1024];
__device__ float g_gx[NSAMP * 2048];
__device__ float g_ghh[2 * 64 * 2048];
__device__ float g_h[64 * 512];
__device__ float g_c[64 * 512];
__device__ float g_hidden[NSAMP * 512];

// ---------------------------------------------------------------------------
// conv1: grid (1024, 3 row-strips), 320 thr, 2 blocks/SM.
// smem: input 4x32x88 (strip, padded) + weights 32x4x28 (f4-padded) = 59392 B
// ---------------------------------------------------------------------------
__global__ void __launch_bounds__(320, 2) conv1_kernel(const float* __restrict__ x,
                                                       const float* __restrict__ w,
                                                       const float* __restrict__ bias) {
    extern __shared__ float sm[];
    float* s_in = sm;                 // 4*32*88 = 11264
    float* s_w  = sm + 11264;         // 32*4*28 = 3584
    const int n = blockIdx.x;
    const int strip = blockIdx.y;     // pooled rows [14*strip, 14*strip+14)

    for (int i = threadIdx.x; i < 11264; i += blockDim.x) {
        int ic = i / 2816;
        int rem = i % 2816;
        int r = rem / 88, c = rem % 88;
        int y = 28 * strip - 2 + r, xx = c - 2;
        float v = 0.f;
        if ((unsigned)y < 84u && (unsigned)xx < 84u)
            v = x[((n * 4 + ic) * 84 + y) * 84 + xx];
        s_in[i] = v;
    }
    for (int i = threadIdx.x; i < 3584; i += blockDim.x) {
        int k = i % 28, oi = i / 28;
        s_w[i] = (k < 25) ? w[oi * 25 + k] : 0.f;
    }
    __syncthreads();

    for (int p = threadIdx.x; p < 16 * 14 * 42; p += blockDim.x) {
        int ocp = p / 588;
        int rem = p % 588;
        int py = rem / 42, px = rem % 42;
        int oc = ocp, oc2 = ocp + 16;
        float acc0[2][2] = {{0.f,0.f},{0.f,0.f}};
        float acc1[2][2] = {{0.f,0.f},{0.f,0.f}};
        #pragma unroll
        for (int ic = 0; ic < 4; ic++) {
            float wreg[56];
            float4* wv = (float4*)wreg;
            const float4* wa4 = (const float4*)(s_w + (oc  * 4 + ic) * 28);
            const float4* wb4 = (const float4*)(s_w + (oc2 * 4 + ic) * 28);
            #pragma unroll
            for (int j = 0; j < 7; j++) { wv[j] = wa4[j]; wv[7 + j] = wb4[j]; }
            const float* wa = wreg;
            const float* wb = wreg + 28;
            const float* sp = s_in + ic * 2816 + (2 * py) * 88 + 2 * px;
            #pragma unroll
            for (int r = 0; r < 6; r++) {
                float2 v01 = *(const float2*)(sp + r * 88);
                float2 v23 = *(const float2*)(sp + r * 88 + 2);
                float2 v45 = *(const float2*)(sp + r * 88 + 4);
                float v[6] = {v01.x, v01.y, v23.x, v23.y, v45.x, v45.y};
                #pragma unroll
                for (int dy = 0; dy < 2; dy++) {
                    int ky = r - dy;
                    if (ky >= 0 && ky < 5) {
                        #pragma unroll
                        for (int kx = 0; kx < 5; kx++) {
                            float w0 = wa[ky * 5 + kx], w1v = wb[ky * 5 + kx];
                            acc0[dy][0] += w0  * v[kx];
                            acc0[dy][1] += w0  * v[kx + 1];
                            acc1[dy][0] += w1v * v[kx];
                            acc1[dy][1] += w1v * v[kx + 1];
                        }
                    }
                }
            }
        }
        int pyg = 14 * strip + py;
        float m0 = fmaxf(fmaxf(acc0[0][0], acc0[0][1]), fmaxf(acc0[1][0], acc0[1][1])) + bias[oc];
        float m1 = fmaxf(fmaxf(acc1[0][0], acc1[0][1]), fmaxf(acc1[1][0], acc1[1][1])) + bias[oc2];
        g_a1[((n * 32 + oc ) * 42 + pyg) * 42 + px] = fmaxf(m0, 0.f);
        g_a1[((n * 32 + oc2) * 42 + pyg) * 42 + px] = fmaxf(m1, 0.f);
    }
}

// ---------------------------------------------------------------------------
// conv2: grid (1024, 5 row-strips, 4 oc-splits), 320 thr (1 task each), 2 blk/SM.
// smem: input 32x12x44 + weights 4ocp x 32ic x 2 x 28 = 96256 B
// ---------------------------------------------------------------------------
__global__ void __launch_bounds__(320, 2) conv2_kernel(const float* __restrict__ w,
                                                       const float* __restrict__ bias) {
    extern __shared__ float sm[];
    float* s_in = sm;                 // 32*12*44 = 16896
    float* s_w  = sm + 16896;         // 4*32*2*28 = 7168
    const int n = blockIdx.x;
    const int by = blockIdx.y;        // pooled rows [4*by, 4*by+4)
    const int q  = blockIdx.z;        // oc pairs [4q, 4q+4)

    for (int i = threadIdx.x; i < 16896; i += blockDim.x) {
        int ic = i / 528;
        int rem = i % 528;
        int rr = rem / 44, cc = rem % 44;
        int y = 8 * by - 1 + rr, xx = cc - 1;
        float v = 0.f;
        if ((unsigned)y < 42u && (unsigned)xx < 42u)
            v = g_a1[((n * 32 + ic) * 42 + y) * 42 + xx];
        s_in[i] = v;
    }
    for (int i = threadIdx.x; i < 7168; i += blockDim.x) {
        int lp = i / 1792;
        int rem = i % 1792;
        int ic = rem / 56;
        int half = (rem % 56) / 28;
        int k = rem % 28;
        int oc = 4 * q + lp + half * 16;
        s_w[i] = (k < 25) ? w[(oc * 32 + ic) * 25 + k] : 0.f;
    }
    __syncthreads();

    {
        int tid = threadIdx.x;
        int lp = tid / 80;
        int rem = tid % 80;
        int py = rem / 20, px = rem % 20;
        int oc = 4 * q + lp, oc2 = oc + 16;
        float acc0[2][2] = {{0.f,0.f},{0.f,0.f}};
        float acc1[2][2] = {{0.f,0.f},{0.f,0.f}};
        #pragma unroll 2
        for (int ic = 0; ic < 32; ic++) {
            float wreg[56];
            float4* wv = (float4*)wreg;
            const float4* wa4 = (const float4*)(s_w + ((lp * 32 + ic) * 2    ) * 28);
            const float4* wb4 = (const float4*)(s_w + ((lp * 32 + ic) * 2 + 1) * 28);
            #pragma unroll
            for (int j = 0; j < 7; j++) { wv[j] = wa4[j]; wv[7 + j] = wb4[j]; }
            const float* wa = wreg;
            const float* wb = wreg + 28;
            const float* sp = s_in + ic * 528 + (2 * py) * 44 + 2 * px;
            #pragma unroll
            for (int r = 0; r < 6; r++) {
                float2 v01 = *(const float2*)(sp + r * 44);
                float2 v23 = *(const float2*)(sp + r * 44 + 2);
                float2 v45 = *(const float2*)(sp + r * 44 + 4);
                float v[6] = {v01.x, v01.y, v23.x, v23.y, v45.x, v45.y};
                #pragma unroll
                for (int dy = 0; dy < 2; dy++) {
                    int ky = r - dy;
                    if (ky >= 0 && ky < 5) {
                        #pragma unroll
                        for (int kx = 0; kx < 5; kx++) {
                            float w0 = wa[ky * 5 + kx], w1v = wb[ky * 5 + kx];
                            acc0[dy][0] += w0  * v[kx];
                            acc0[dy][1] += w0  * v[kx + 1];
                            acc1[dy][0] += w1v * v[kx];
                            acc1[dy][1] += w1v * v[kx + 1];
                        }
                    }
                }
            }
        }
        int pyg = 4 * by + py;
        float m0 = fmaxf(fmaxf(acc0[0][0], acc0[0][1]), fmaxf(acc0[1][0], acc0[1][1])) + bias[oc];
        float m1 = fmaxf(fmaxf(acc1[0][0], acc1[0][1]), fmaxf(acc1[1][0], acc1[1][1])) + bias[oc2];
        g_a2[((n * 32 + oc ) * 20 + pyg) * 20 + px] = fmaxf(m0, 0.f);
        g_a2[((n * 32 + oc2) * 20 + pyg) * 20 + px] = fmaxf(m1, 0.f);
    }
}

// ---------------------------------------------------------------------------
// conv3: grid (1024, 8 oc-splits), 352 thr, 2 blk/SM.
// smem: input 32x21x22 (stride padded) + weights 4x32x2x16 = 75520 B
// ---------------------------------------------------------------------------
__global__ void __launch_bounds__(352, 2) conv3_kernel(const float* __restrict__ w,
                                                       const float* __restrict__ bias) {
    extern __shared__ float sm[];
    float* s_in = sm;                 // 32*21*22 = 14784
    float* s_w  = sm + 14784;         // 4*32*2*16 = 4096
    const int n = blockIdx.x;
    const int q = blockIdx.y;         // oc pairs [4q, 4q+4), pair = (oc, oc+32)

    for (int i = threadIdx.x; i < 14784; i += blockDim.x) {
        int ic = i / 462;
        int rem = i % 462;
        int r = rem / 22, c = rem % 22;
        float v = 0.f;
        if (c < 21) {
            int y = r - 1, xx = c - 1;
            if ((unsigned)y < 20u && (unsigned)xx < 20u)
                v = g_a2[((n * 32 + ic) * 20 + y) * 20 + xx];
        }
        s_in[i] = v;
    }
    for (int i = threadIdx.x; i < 4096; i += blockDim.x) {
        int lp = i / 1024;
        int rem = i % 1024;
        int ic = rem / 32;
        int half = (rem % 32) / 16;
        int k = rem % 16;
        int oc = 4 * q + lp + half * 32;
        s_w[i] = w[(oc * 32 + ic) * 16 + k];
    }
    __syncthreads();

    int tid = threadIdx.x;
    if (tid < 324) {
        int lp = tid / 81;
        int rem = tid % 81;
        int py = rem / 9, px = rem % 9;
        int oc = 4 * q + lp, oc2 = oc + 32;
        float acc0[2][2] = {{0.f,0.f},{0.f,0.f}};
        float acc1[2][2] = {{0.f,0.f},{0.f,0.f}};
        #pragma unroll 2
        for (int ic = 0; ic < 32; ic++) {
            float wreg[32];
            float4* wv = (float4*)wreg;
            const float4* wa4 = (const float4*)(s_w + ((lp * 32 + ic) * 2    ) * 16);
            const float4* wb4 = (const float4*)(s_w + ((lp * 32 + ic) * 2 + 1) * 16);
            #pragma unroll
            for (int j = 0; j < 4; j++) { wv[j] = wa4[j]; wv[4 + j] = wb4[j]; }
            const float* wa = wreg;
            const float* wb = wreg + 16;
            const float* sp = s_in + ic * 462 + (2 * py) * 22 + 2 * px;
            #pragma unroll
            for (int r = 0; r < 5; r++) {
                float2 v01 = *(const float2*)(sp + r * 22);
                float2 v23 = *(const float2*)(sp + r * 22 + 2);
                float v[5] = {v01.x, v01.y, v23.x, v23.y, sp[r * 22 + 4]};
                #pragma unroll
                for (int dy = 0; dy < 2; dy++) {
                    int ky = r - dy;
                    if (ky >= 0 && ky < 4) {
                        #pragma unroll
                        for (int kx = 0; kx < 4; kx++) {
                            float w0 = wa[ky * 4 + kx], w1v = wb[ky * 4 + kx];
                            acc0[dy][0] += w0  * v[kx];
                            acc0[dy][1] += w0  * v[kx + 1];
                            acc1[dy][0] += w1v * v[kx];
                            acc1[dy][1] += w1v * v[kx + 1];
                        }
                    }
                }
            }
        }
        float m0 = fmaxf(fmaxf(acc0[0][0], acc0[0][1]), fmaxf(acc0[1][0], acc0[1][1])) + bias[oc];
        float m1 = fmaxf(fmaxf(acc1[0][0], acc1[0][1]), fmaxf(acc1[1][0], acc1[1][1])) + bias[oc2];
        g_a3[((n * 64 + oc ) * 9 + py) * 9 + px] = fmaxf(m0, 0.f);
        g_a3[((n * 64 + oc2) * 9 + py) * 9 + px] = fmaxf(m1, 0.f);
    }
}

// ---------------------------------------------------------------------------
// conv4: per-sample, 512 thr (1 task each). weights f4-padded (9->12).
// smem: 8448 + 64*64*12 = 230400 B
// ---------------------------------------------------------------------------
__global__ void __launch_bounds__(512) conv4_kernel(const float* __restrict__ w,
                                                    const float* __restrict__ bias) {
    extern __shared__ float sm[];
    float* s_in = sm;                 // 64*11*12 = 8448
    float* s_w  = sm + 8448;          // 64*64*12 = 49152
    const int n = blockIdx.x;

    for (int i = threadIdx.x; i < 8448; i += blockDim.x) {
        int ic = i / 132;
        int rem = i % 132;
        int r = rem / 12, c = rem % 12;
        int y = r - 1, xx = c - 1;
        float v = 0.f;
        if ((unsigned)y < 9u && (unsigned)xx < 9u)
            v = g_a3[((n * 64 + ic) * 9 + y) * 9 + xx];
        s_in[i] = v;
    }
    for (int i = threadIdx.x; i < 49152; i += blockDim.x) {
        int k = i % 12, oi = i / 12;
        s_w[i] = (k < 9) ? w[oi * 9 + k] : 0.f;
    }
    __syncthreads();

    {
        int tid = threadIdx.x;
        int ocp = tid / 16;
        int rem = tid % 16;
        int py = rem / 4, px = rem % 4;
        int oc = ocp, oc2 = ocp + 32;
        float acc0[2][2] = {{0.f,0.f},{0.f,0.f}};
        float acc1[2][2] = {{0.f,0.f},{0.f,0.f}};
        #pragma unroll 4
        for (int ic = 0; ic < 64; ic++) {
            float wreg[24];
            float4* wv = (float4*)wreg;
            const float4* wa4 = (const float4*)(s_w + (oc  * 64 + ic) * 12);
            const float4* wb4 = (const float4*)(s_w + (oc2 * 64 + ic) * 12);
            #pragma unroll
            for (int j = 0; j < 3; j++) { wv[j] = wa4[j]; wv[3 + j] = wb4[j]; }
            const float* wa = wreg;
            const float* wb = wreg + 12;
            const float* sp = s_in + ic * 132 + (2 * py) * 12 + 2 * px;
            #pragma unroll
            for (int r = 0; r < 4; r++) {
                float2 v01 = *(const float2*)(sp + r * 12);
                float2 v23 = *(const float2*)(sp + r * 12 + 2);
                float v[4] = {v01.x, v01.y, v23.x, v23.y};
                #pragma unroll
                for (int dy = 0; dy < 2; dy++) {
                    int ky = r - dy;
                    if (ky >= 0 && ky < 3) {
                        #pragma unroll
                        for (int kx = 0; kx < 3; kx++) {
                            float w0 = wa[ky * 3 + kx], w1v = wb[ky * 3 + kx];
                            acc0[dy][0] += w0  * v[kx];
                            acc0[dy][1] += w0  * v[kx + 1];
                            acc1[dy][0] += w1v * v[kx];
                            acc1[dy][1] += w1v * v[kx + 1];
                        }
                    }
                }
            }
        }
        float m0 = fmaxf(fmaxf(acc0[0][0], acc0[0][1]), fmaxf(acc0[1][0], acc0[1][1])) + bias[oc];
        float m1 = fmaxf(fmaxf(acc1[0][0], acc1[0][1]), fmaxf(acc1[1][0], acc1[1][1])) + bias[oc2];
        g_feat[n * 1024 + oc  * 16 + py * 4 + px] = fmaxf(m0, 0.f);
        g_feat[n * 1024 + oc2 * 16 + py * 4 + px] = fmaxf(m1, 0.f);
    }
}

// ---------------------------------------------------------------------------
// GEMM  C[M,N] = A[M,K] @ B[N,K]^T
// ---------------------------------------------------------------------------
template <int BM, int BN, int BK, int TM, int TN, bool MASK, bool SPLITK>
__device__ __forceinline__ void gemm_body(const float* __restrict__ A,
                                          const float* __restrict__ B,
                                          float* __restrict__ C,
                                          int M, int N, int K,
                                          const float* __restrict__ dvec) {
    __shared__ float As[BK][BM + 4];
    __shared__ float Bs[BK][BN + 4];
    constexpr int NT = (BM / TM) * (BN / TN);
    const int tid = threadIdx.x;
    const int tx = tid % (BN / TN);
    const int ty = tid / (BN / TN);
    const int m0 = blockIdx.y * BM;
    const int n0 = blockIdx.x * BN;
    int kBeg = 0, kEnd = K;
    if (SPLITK) {
        int kc = K / gridDim.z;
        kBeg = blockIdx.z * kc;
        kEnd = kBeg + kc;
        C += (size_t)blockIdx.z * M * N;
    }
    float acc[TM][TN];
    #pragma unroll
    for (int i = 0; i < TM; i++)
        #pragma unroll
        for (int j = 0; j < TN; j++) acc[i][j] = 0.f;

    for (int kk = kBeg; kk < kEnd; kk += BK) {
        for (int i = tid; i < BM * BK; i += NT) {
            int r = i / BK, c = i % BK;
            float v = A[(m0 + r) * K + kk + c];
            if (MASK) v *= (1.0f - dvec[m0 + r]);
            As[c][r] = v;
        }
        for (int i = tid; i < BN * BK; i += NT) {
            int r = i / BK, c = i % BK;
            Bs[c][r] = B[(n0 + r) * K + kk + c];
        }
        __syncthreads();
        #pragma unroll
        for (int k = 0; k < BK; k++) {
            float a[TM], b[TN];
            #pragma unroll
            for (int i = 0; i < TM; i++) a[i] = As[k][ty * TM + i];
            #pragma unroll
            for (int j = 0; j < TN; j++) b[j] = Bs[k][tx * TN + j];
            #pragma unroll
            for (int i = 0; i < TM; i++)
                #pragma unroll
                for (int j = 0; j < TN; j++) acc[i][j] += a[i] * b[j];
        }
        __syncthreads();
    }
    #pragma unroll
    for (int i = 0; i < TM; i++)
        #pragma unroll
        for (int j = 0; j < TN; j++)
            C[(size_t)(m0 + ty * TM + i) * N + n0 + tx * TN + j] = acc[i][j];
}

__global__ void __launch_bounds__(256) gemm_gx_kernel(const float* __restrict__ W_ih) {
    gemm_body<64, 64, 16, 4, 4, false, false>(g_feat, W_ih, g_gx, 1024, 2048, 1024, nullptr);
}

__global__ void __launch_bounds__(256) gemm_hh_kernel(const float* __restrict__ W_hh,
                                                      const float* __restrict__ done, int t) {
    gemm_body<64, 32, 16, 4, 2, true, true>(g_h, W_hh, g_ghh, 64, 2048, 512, done + t * 64);
}

// ---------------------------------------------------------------------------
__device__ __forceinline__ float sigm(float x) { return 1.f / (1.f + expf(-x)); }

__global__ void lstm_update_kernel(const float* __restrict__ b_ih,
                                   const float* __restrict__ b_hh,
                                   const float* __restrict__ done, int t) {
    int idx = blockIdx.x * blockDim.x + threadIdx.x;
    if (idx >= 64 * 512) return;
    int b = idx / 512, j = idx % 512;
    int n = t * 64 + b;
    const float* gx = g_gx + (size_t)n * 2048;
    const float* g1 = g_ghh + (size_t)b * 2048;
    const float* g2 = g_ghh + 64 * 2048 + (size_t)b * 2048;

    float gi = gx[j]        + g1[j]        + g2[j]        + b_ih[j]        + b_hh[j];
    float gf = gx[512 + j]  + g1[512 + j]  + g2[512 + j]  + b_ih[512 + j]  + b_hh[512 + j];
    float gg = gx[1024 + j] + g1[1024 + j] + g2[1024 + j] + b_ih[1024 + j] + b_hh[1024 + j];
    float go = gx[1536 + j] + g1[1536 + j] + g2[1536 + j] + b_ih[1536 + j] + b_hh[1536 + j];

    float m = 1.0f - done[n];
    float c = g_c[idx] * m;
    float cn = sigm(gf) * c + sigm(gi) * tanhf(gg);
    float hn = sigm(go) * tanhf(cn);
    g_c[idx] = cn;
    g_h[idx] = hn;
    g_hidden[(size_t)n * 512 + j] = hn;
}

// ---------------------------------------------------------------------------
__global__ void __launch_bounds__(256) head_kernel(const float* __restrict__ Wa,
                                                   const float* __restrict__ ba,
                                                   const float* __restrict__ Wc,
                                                   const float* __restrict__ bc,
                                                   float* __restrict__ out) {
    int warp = threadIdx.x / 32, lane = threadIdx.x % 32;
    int n = blockIdx.x * 8 + warp;
    float h[16];
    #pragma unroll
    for (int i = 0; i < 16; i++) h[i] = g_hidden[(size_t)n * 512 + i * 32 + lane];
    for (int j = 0; j < 19; j++) {
        const float* w = (j < 18) ? (Wa + j * 512) : Wc;
        float s = 0.f;
        #pragma unroll
        for (int i = 0; i < 16; i++) s += h[i] * w[i * 32 + lane];
        #pragma unroll
        for (int o = 16; o; o >>= 1) s += __shfl_xor_sync(0xffffffffu, s, o);
        if (lane == 0) out[n * 19 + j] = s + ((j < 18) ? ba[j] : bc[0]);
    }
}

__global__ void init_state_kernel(const float* __restrict__ h0, const float* __restrict__ c0) {
    int idx = blockIdx.x * blockDim.x + threadIdx.x;
    if (idx < 64 * 512) { g_h[idx] = h0[idx]; g_c[idx] = c0[idx]; }
}

__global__ void copy_out_kernel(float* __restrict__ out) {
    int idx = blockIdx.x * blockDim.x + threadIdx.x;
    if (idx < 64 * 512) {
        out[19456 + idx] = g_h[idx];
        out[19456 + 32768 + idx] = g_c[idx];
    }
}

// ---------------------------------------------------------------------------
extern "C" void kernel_launch(void* const* d_in, const int* in_sizes, int n_in,
                              void* d_out, int out_size) {
    const float* x    = (const float*)d_in[0];
    const float* done = (const float*)d_in[1];
    const float* h0   = (const float*)d_in[2];
    const float* c0   = (const float*)d_in[3];
    const float* w1   = (const float*)d_in[4];
    const float* b1   = (const float*)d_in[5];
    const float* w2   = (const float*)d_in[6];
    const float* b2   = (const float*)d_in[7];
    const float* w3   = (const float*)d_in[8];
    const float* b3   = (const float*)d_in[9];
    const float* w4   = (const float*)d_in[10];
    const float* b4   = (const float*)d_in[11];
    const float* W_ih = (const float*)d_in[12];
    const float* W_hh = (const float*)d_in[13];
    const float* b_ih = (const float*)d_in[14];
    const float* b_hh = (const float*)d_in[15];
    const float* Wa   = (const float*)d_in[16];
    const float* ba   = (const float*)d_in[17];
    const float* Wc   = (const float*)d_in[18];
    const float* bc   = (const float*)d_in[19];
    float* out = (float*)d_out;

    const int SM1 = (11264 + 3584) * 4;   // 59392
    const int SM2 = (16896 + 7168) * 4;   // 96256
    const int SM3 = (14784 + 4096) * 4;   // 75520
    const int SM4 = (8448 + 49152) * 4;   // 230400
    cudaFuncSetAttribute(conv1_kernel, cudaFuncAttributeMaxDynamicSharedMemorySize, SM1);
    cudaFuncSetAttribute(conv2_kernel, cudaFuncAttributeMaxDynamicSharedMemorySize, SM2);
    cudaFuncSetAttribute(conv3_kernel, cudaFuncAttributeMaxDynamicSharedMemorySize, SM3);
    cudaFuncSetAttribute(conv4_kernel, cudaFuncAttributeMaxDynamicSharedMemorySize, SM4);

    init_state_kernel<<<128, 256>>>(h0, c0);

    conv1_kernel<<<dim3(NSAMP, 3), 320, SM1>>>(x, w1, b1);
    conv2_kernel<<<dim3(NSAMP, 5, 4), 320, SM2>>>(w2, b2);
    conv3_kernel<<<dim3(NSAMP, 8), 352, SM3>>>(w3, b3);
    conv4_kernel<<<NSAMP, 512, SM4>>>(w4, b4);

    gemm_gx_kernel<<<dim3(2048 / 64, 1024 / 64, 1), 256>>>(W_ih);

    for (int t = 0; t < 16; t++) {
        gemm_hh_kernel<<<dim3(2048 / 32, 1, 2), 256>>>(W_hh, done, t);
        lstm_update_kernel<<<128, 256>>>(b_ih, b_hh, done, t);
    }

    head_kernel<<<NSAMP / 8, 256>>>(Wa, ba, Wc, bc, out);
    copy_out_kernel<<<128, 256>>>(out);
}

// round 9
// speedup vs baseline: 1.0317x; 1.0317x over previous
#include <cuda_runtime.h>
#include <cuda_bf16.h>
#include <math.h>

// ---------------------------------------------------------------------------
//  x (1024,4,84,84) -> conv1 5x5 p2 -> pool -> relu : a1 (1024,32,42,42)
//  conv2 5x5 p1 -> pool -> relu : a2 (1024,32,20,20)
//  conv3 4x4 p1 -> pool -> relu : a3 (1024,64,9,9)
//  conv4 3x3 p1 -> pool -> relu -> flatten : feat (1024,1024)
//  LSTM T=16 B=64 H=512 ; heads -> out (1024,19) + hT + cT
//
//  Scalar fp32 convs (no tensor mma — that path is abandoned on this stack),
//  optimized for issue-slot economy: f4-padded weight staging (LDS.128),
//  aligned float2 input loads, R1 grids (no oc-splits).
// ---------------------------------------------------------------------------

#define NSAMP 1024

__device__ float g_a1[NSAMP * 32 * 42 * 42];
__device__ float g_a2[NSAMP * 32 * 20 * 20];
__device__ float g_a3[NSAMP * 64 * 9 * 9];
__device__ float g_feat[NSAMP * 1024];
__device__ float g_gx[NSAMP * 2048];
__device__ float g_ghh[2 * 64 * 2048];
__device__ float g_h[64 * 512];
__device__ float g_c[64 * 512];
__device__ float g_hidden[NSAMP * 512];

// ---------------------------------------------------------------------------
// conv1: grid (1024, 3 row-strips), 320 thr, 2 blocks/SM. smem 59392 B
// ---------------------------------------------------------------------------
__global__ void __launch_bounds__(320, 2) conv1_kernel(const float* __restrict__ x,
                                                       const float* __restrict__ w,
                                                       const float* __restrict__ bias) {
    extern __shared__ float sm[];
    float* s_in = sm;                 // 4*32*88 = 11264
    float* s_w  = sm + 11264;         // 32*4*28 = 3584
    const int n = blockIdx.x;
    const int strip = blockIdx.y;     // pooled rows [14*strip, 14*strip+14)

    for (int i = threadIdx.x; i < 11264; i += blockDim.x) {
        int ic = i / 2816;
        int rem = i % 2816;
        int r = rem / 88, c = rem % 88;
        int y = 28 * strip - 2 + r, xx = c - 2;
        float v = 0.f;
        if ((unsigned)y < 84u && (unsigned)xx < 84u)
            v = x[((n * 4 + ic) * 84 + y) * 84 + xx];
        s_in[i] = v;
    }
    for (int i = threadIdx.x; i < 3584; i += blockDim.x) {
        int k = i % 28, oi = i / 28;
        s_w[i] = (k < 25) ? w[oi * 25 + k] : 0.f;
    }
    __syncthreads();

    for (int p = threadIdx.x; p < 16 * 14 * 42; p += blockDim.x) {
        int ocp = p / 588;
        int rem = p % 588;
        int py = rem / 42, px = rem % 42;
        int oc = ocp, oc2 = ocp + 16;
        float acc0[2][2] = {{0.f,0.f},{0.f,0.f}};
        float acc1[2][2] = {{0.f,0.f},{0.f,0.f}};
        #pragma unroll
        for (int ic = 0; ic < 4; ic++) {
            float wreg[56];
            float4* wv = (float4*)wreg;
            const float4* wa4 = (const float4*)(s_w + (oc  * 4 + ic) * 28);
            const float4* wb4 = (const float4*)(s_w + (oc2 * 4 + ic) * 28);
            #pragma unroll
            for (int j = 0; j < 7; j++) { wv[j] = wa4[j]; wv[7 + j] = wb4[j]; }
            const float* wa = wreg;
            const float* wb = wreg + 28;
            const float* sp = s_in + ic * 2816 + (2 * py) * 88 + 2 * px;
            #pragma unroll
            for (int r = 0; r < 6; r++) {
                float2 v01 = *(const float2*)(sp + r * 88);
                float2 v23 = *(const float2*)(sp + r * 88 + 2);
                float2 v45 = *(const float2*)(sp + r * 88 + 4);
                float v[6] = {v01.x, v01.y, v23.x, v23.y, v45.x, v45.y};
                #pragma unroll
                for (int dy = 0; dy < 2; dy++) {
                    int ky = r - dy;
                    if (ky >= 0 && ky < 5) {
                        #pragma unroll
                        for (int kx = 0; kx < 5; kx++) {
                            float w0 = wa[ky * 5 + kx], w1v = wb[ky * 5 + kx];
                            acc0[dy][0] += w0  * v[kx];
                            acc0[dy][1] += w0  * v[kx + 1];
                            acc1[dy][0] += w1v * v[kx];
                            acc1[dy][1] += w1v * v[kx + 1];
                        }
                    }
                }
            }
        }
        int pyg = 14 * strip + py;
        float m0 = fmaxf(fmaxf(acc0[0][0], acc0[0][1]), fmaxf(acc0[1][0], acc0[1][1])) + bias[oc];
        float m1 = fmaxf(fmaxf(acc1[0][0], acc1[0][1]), fmaxf(acc1[1][0], acc1[1][1])) + bias[oc2];
        g_a1[((n * 32 + oc ) * 42 + pyg) * 42 + px] = fmaxf(m0, 0.f);
        g_a1[((n * 32 + oc2) * 42 + pyg) * 42 + px] = fmaxf(m1, 0.f);
    }
}

// ---------------------------------------------------------------------------
// conv2: R1 grid (1024, 4 strips of 5 pooled rows), 320 thr.
// smem: input 32*14*44 + weights padded 32*32*2*28/2... full 1024 oi*28
//   = 19712 + 28672 floats = 193536 B
// ---------------------------------------------------------------------------
__global__ void __launch_bounds__(320) conv2_kernel(const float* __restrict__ w,
                                                    const float* __restrict__ bias) {
    extern __shared__ float sm[];
    float* s_in = sm;                 // 32*14*44 = 19712
    float* s_w  = sm + 19712;         // 1024*28 = 28672
    const int n = blockIdx.x;
    const int py0 = 5 * blockIdx.y;

    for (int i = threadIdx.x; i < 19712; i += blockDim.x) {
        int ic = i / 616;
        int rem = i % 616;
        int rr = rem / 44, cc = rem % 44;
        int y = 2 * py0 - 1 + rr;
        int xx = cc - 1;
        float v = 0.f;
        if ((unsigned)y < 42u && (unsigned)xx < 42u)
            v = g_a1[((n * 32 + ic) * 42 + y) * 42 + xx];
        s_in[i] = v;
    }
    for (int i = threadIdx.x; i < 28672; i += blockDim.x) {
        int k = i % 28, oi = i / 28;
        s_w[i] = (k < 25) ? w[oi * 25 + k] : 0.f;
    }
    __syncthreads();

    for (int p = threadIdx.x; p < 16 * 5 * 20; p += blockDim.x) {
        int oc = p / 100;
        int rem = p % 100;
        int lpy = rem / 20, px = rem % 20;
        int oc2 = oc + 16;
        float acc0[2][2] = {{0.f,0.f},{0.f,0.f}};
        float acc1[2][2] = {{0.f,0.f},{0.f,0.f}};
        #pragma unroll 2
        for (int ic = 0; ic < 32; ic++) {
            float wreg[56];
            float4* wv = (float4*)wreg;
            const float4* wa4 = (const float4*)(s_w + (oc  * 32 + ic) * 28);
            const float4* wb4 = (const float4*)(s_w + (oc2 * 32 + ic) * 28);
            #pragma unroll
            for (int j = 0; j < 7; j++) { wv[j] = wa4[j]; wv[7 + j] = wb4[j]; }
            const float* wa = wreg;
            const float* wb = wreg + 28;
            const float* sp = s_in + ic * 616 + (2 * lpy) * 44 + 2 * px;
            #pragma unroll
            for (int r = 0; r < 6; r++) {
                float2 v01 = *(const float2*)(sp + r * 44);
                float2 v23 = *(const float2*)(sp + r * 44 + 2);
                float2 v45 = *(const float2*)(sp + r * 44 + 4);
                float v[6] = {v01.x, v01.y, v23.x, v23.y, v45.x, v45.y};
                #pragma unroll
                for (int dy = 0; dy < 2; dy++) {
                    int ky = r - dy;
                    if (ky >= 0 && ky < 5) {
                        #pragma unroll
                        for (int kx = 0; kx < 5; kx++) {
                            float w0 = wa[ky * 5 + kx], w1v = wb[ky * 5 + kx];
                            acc0[dy][0] += w0  * v[kx];
                            acc0[dy][1] += w0  * v[kx + 1];
                            acc1[dy][0] += w1v * v[kx];
                            acc1[dy][1] += w1v * v[kx + 1];
                        }
                    }
                }
            }
        }
        int py = py0 + lpy;
        float m0 = fmaxf(fmaxf(acc0[0][0], acc0[0][1]), fmaxf(acc0[1][0], acc0[1][1])) + bias[oc];
        float m1 = fmaxf(fmaxf(acc1[0][0], acc1[0][1]), fmaxf(acc1[1][0], acc1[1][1])) + bias[oc2];
        g_a2[((n * 32 + oc ) * 20 + py) * 20 + px] = fmaxf(m0, 0.f);
        g_a2[((n * 32 + oc2) * 20 + py) * 20 + px] = fmaxf(m1, 0.f);
    }
}

// ---------------------------------------------------------------------------
// conv3: R1 grid (1024), 512 thr. input stride padded 21->22 for f2 loads.
// smem: 32*21*22 + 64*32*16 = 14784 + 32768 floats = 190208 B
// ---------------------------------------------------------------------------
__global__ void __launch_bounds__(512) conv3_kernel(const float* __restrict__ w,
                                                    const float* __restrict__ bias) {
    extern __shared__ float sm[];
    float* s_in = sm;            // 32*21*22 = 14784
    float* s_w  = sm + 14784;    // 2048*16 = 32768
    const int n = blockIdx.x;

    for (int i = threadIdx.x; i < 14784; i += blockDim.x) {
        int ic = i / 462;
        int rem = i % 462;
        int r = rem / 22, c = rem % 22;
        float v = 0.f;
        if (c < 21) {
            int y = r - 1, xx = c - 1;
            if ((unsigned)y < 20u && (unsigned)xx < 20u)
                v = g_a2[((n * 32 + ic) * 20 + y) * 20 + xx];
        }
        s_in[i] = v;
    }
    for (int i = threadIdx.x; i < 32768; i += blockDim.x) s_w[i] = w[i];
    __syncthreads();

    for (int p = threadIdx.x; p < 32 * 81; p += blockDim.x) {
        int oc = p / 81;
        int rem = p % 81;
        int py = rem / 9, px = rem % 9;
        int oc2 = oc + 32;
        float acc0[2][2] = {{0.f,0.f},{0.f,0.f}};
        float acc1[2][2] = {{0.f,0.f},{0.f,0.f}};
        #pragma unroll 2
        for (int ic = 0; ic < 32; ic++) {
            float wreg[32];
            float4* wv = (float4*)wreg;
            const float4* wa4 = (const float4*)(s_w + (oc  * 32 + ic) * 16);
            const float4* wb4 = (const float4*)(s_w + (oc2 * 32 + ic) * 16);
            #pragma unroll
            for (int j = 0; j < 4; j++) { wv[j] = wa4[j]; wv[4 + j] = wb4[j]; }
            const float* wa = wreg;
            const float* wb = wreg + 16;
            const float* sp = s_in + ic * 462 + (2 * py) * 22 + 2 * px;
            #pragma unroll
            for (int r = 0; r < 5; r++) {
                float2 v01 = *(const float2*)(sp + r * 22);
                float2 v23 = *(const float2*)(sp + r * 22 + 2);
                float v[5] = {v01.x, v01.y, v23.x, v23.y, sp[r * 22 + 4]};
                #pragma unroll
                for (int dy = 0; dy < 2; dy++) {
                    int ky = r - dy;
                    if (ky >= 0 && ky < 4) {
                        #pragma unroll
                        for (int kx = 0; kx < 4; kx++) {
                            float w0 = wa[ky * 4 + kx], w1v = wb[ky * 4 + kx];
                            acc0[dy][0] += w0  * v[kx];
                            acc0[dy][1] += w0  * v[kx + 1];
                            acc1[dy][0] += w1v * v[kx];
                            acc1[dy][1] += w1v * v[kx + 1];
                        }
                    }
                }
            }
        }
        float m0 = fmaxf(fmaxf(acc0[0][0], acc0[0][1]), fmaxf(acc0[1][0], acc0[1][1])) + bias[oc];
        float m1 = fmaxf(fmaxf(acc1[0][0], acc1[0][1]), fmaxf(acc1[1][0], acc1[1][1])) + bias[oc2];
        g_a3[((n * 64 + oc ) * 9 + py) * 9 + px] = fmaxf(m0, 0.f);
        g_a3[((n * 64 + oc2) * 9 + py) * 9 + px] = fmaxf(m1, 0.f);
    }
}

// ---------------------------------------------------------------------------
// conv4: R1 grid (1024), 512 thr. weights f4-padded 9->12.
// smem: 64*11*12 + 64*64*12 = 8448 + 49152 floats = 230400 B
// ---------------------------------------------------------------------------
__global__ void __launch_bounds__(512) conv4_kernel(const float* __restrict__ w,
                                                    const float* __restrict__ bias) {
    extern __shared__ float sm[];
    float* s_in = sm;                 // 64*132 = 8448
    float* s_w  = sm + 8448;          // 4096*12 = 49152
    const int n = blockIdx.x;

    for (int i = threadIdx.x; i < 8448; i += blockDim.x) {
        int ic = i / 132;
        int rem = i % 132;
        int r = rem / 12, c = rem % 12;
        int y = r - 1, xx = c - 1;
        float v = 0.f;
        if ((unsigned)y < 9u && (unsigned)xx < 9u)
            v = g_a3[((n * 64 + ic) * 9 + y) * 9 + xx];
        s_in[i] = v;
    }
    for (int i = threadIdx.x; i < 49152; i += blockDim.x) {
        int k = i % 12, oi = i / 12;
        s_w[i] = (k < 9) ? w[oi * 9 + k] : 0.f;
    }
    __syncthreads();

    {
        int tid = threadIdx.x;
        int ocp = tid / 16;
        int rem = tid % 16;
        int py = rem / 4, px = rem % 4;
        int oc = ocp, oc2 = ocp + 32;
        float acc0[2][2] = {{0.f,0.f},{0.f,0.f}};
        float acc1[2][2] = {{0.f,0.f},{0.f,0.f}};
        #pragma unroll 4
        for (int ic = 0; ic < 64; ic++) {
            float wreg[24];
            float4* wv = (float4*)wreg;
            const float4* wa4 = (const float4*)(s_w + (oc  * 64 + ic) * 12);
            const float4* wb4 = (const float4*)(s_w + (oc2 * 64 + ic) * 12);
            #pragma unroll
            for (int j = 0; j < 3; j++) { wv[j] = wa4[j]; wv[3 + j] = wb4[j]; }
            const float* wa = wreg;
            const float* wb = wreg + 12;
            const float* sp = s_in + ic * 132 + (2 * py) * 12 + 2 * px;
            #pragma unroll
            for (int r = 0; r < 4; r++) {
                float2 v01 = *(const float2*)(sp + r * 12);
                float2 v23 = *(const float2*)(sp + r * 12 + 2);
                float v[4] = {v01.x, v01.y, v23.x, v23.y};
                #pragma unroll
                for (int dy = 0; dy < 2; dy++) {
                    int ky = r - dy;
                    if (ky >= 0 && ky < 3) {
                        #pragma unroll
                        for (int kx = 0; kx < 3; kx++) {
                            float w0 = wa[ky * 3 + kx], w1v = wb[ky * 3 + kx];
                            acc0[dy][0] += w0  * v[kx];
                            acc0[dy][1] += w0  * v[kx + 1];
                            acc1[dy][0] += w1v * v[kx];
                            acc1[dy][1] += w1v * v[kx + 1];
                        }
                    }
                }
            }
        }
        float m0 = fmaxf(fmaxf(acc0[0][0], acc0[0][1]), fmaxf(acc0[1][0], acc0[1][1])) + bias[oc];
        float m1 = fmaxf(fmaxf(acc1[0][0], acc1[0][1]), fmaxf(acc1[1][0], acc1[1][1])) + bias[oc2];
        g_feat[n * 1024 + oc  * 16 + py * 4 + px] = fmaxf(m0, 0.f);
        g_feat[n * 1024 + oc2 * 16 + py * 4 + px] = fmaxf(m1, 0.f);
    }
}

// ---------------------------------------------------------------------------
// GEMM  C[M,N] = A[M,K] @ B[N,K]^T
// ---------------------------------------------------------------------------
template <int BM, int BN, int BK, int TM, int TN, bool MASK, bool SPLITK>
__device__ __forceinline__ void gemm_body(const float* __restrict__ A,
                                          const float* __restrict__ B,
                                          float* __restrict__ C,
                                          int M, int N, int Kd,
                                          const float* __restrict__ dvec) {
    __shared__ float As[BK][BM + 4];
    __shared__ float Bs[BK][BN + 4];
    constexpr int NTr = (BM / TM) * (BN / TN);
    const int tid = threadIdx.x;
    const int tx = tid % (BN / TN);
    const int ty = tid / (BN / TN);
    const int m0 = blockIdx.y * BM;
    const int n0 = blockIdx.x * BN;
    int kBeg = 0, kEnd = Kd;
    if (SPLITK) {
        int kc = Kd / gridDim.z;
        kBeg = blockIdx.z * kc;
        kEnd = kBeg + kc;
        C += (size_t)blockIdx.z * M * N;
    }
    float acc[TM][TN];
    #pragma unroll
    for (int i = 0; i < TM; i++)
        #pragma unroll
        for (int j = 0; j < TN; j++) acc[i][j] = 0.f;

    for (int kk = kBeg; kk < kEnd; kk += BK) {
        for (int i = tid; i < BM * BK; i += NTr) {
            int r = i / BK, c = i % BK;
            float v = A[(m0 + r) * Kd + kk + c];
            if (MASK) v *= (1.0f - dvec[m0 + r]);
            As[c][r] = v;
        }
        for (int i = tid; i < BN * BK; i += NTr) {
            int r = i / BK, c = i % BK;
            Bs[c][r] = B[(n0 + r) * Kd + kk + c];
        }
        __syncthreads();
        #pragma unroll
        for (int k = 0; k < BK; k++) {
            float a[TM], b[TN];
            #pragma unroll
            for (int i = 0; i < TM; i++) a[i] = As[k][ty * TM + i];
            #pragma unroll
            for (int j = 0; j < TN; j++) b[j] = Bs[k][tx * TN + j];
            #pragma unroll
            for (int i = 0; i < TM; i++)
                #pragma unroll
                for (int j = 0; j < TN; j++) acc[i][j] += a[i] * b[j];
        }
        __syncthreads();
    }
    #pragma unroll
    for (int i = 0; i < TM; i++)
        #pragma unroll
        for (int j = 0; j < TN; j++)
            C[(size_t)(m0 + ty * TM + i) * N + n0 + tx * TN + j] = acc[i][j];
}

__global__ void __launch_bounds__(256) gemm_gx_kernel(const float* __restrict__ W_ih) {
    gemm_body<64, 64, 16, 4, 4, false, false>(g_feat, W_ih, g_gx, 1024, 2048, 1024, nullptr);
}

__global__ void __launch_bounds__(256) gemm_hh_kernel(const float* __restrict__ W_hh,
                                                      const float* __restrict__ done, int t) {
    gemm_body<64, 32, 16, 4, 2, true, true>(g_h, W_hh, g_ghh, 64, 2048, 512, done + t * 64);
}

// ---------------------------------------------------------------------------
__device__ __forceinline__ float sigm(float x) { return 1.f / (1.f + expf(-x)); }

__global__ void lstm_update_kernel(const float* __restrict__ b_ih,
                                   const float* __restrict__ b_hh,
                                   const float* __restrict__ done, int t) {
    int idx = blockIdx.x * blockDim.x + threadIdx.x;
    if (idx >= 64 * 512) return;
    int b = idx / 512, j = idx % 512;
    int n = t * 64 + b;
    const float* gx = g_gx + (size_t)n * 2048;
    const float* g1 = g_ghh + (size_t)b * 2048;
    const float* g2 = g_ghh + 64 * 2048 + (size_t)b * 2048;

    float gi = gx[j]        + g1[j]        + g2[j]        + b_ih[j]        + b_hh[j];
    float gf = gx[512 + j]  + g1[512 + j]  + g2[512 + j]  + b_ih[512 + j]  + b_hh[512 + j];
    float gg = gx[1024 + j] + g1[1024 + j] + g2[1024 + j] + b_ih[1024 + j] + b_hh[1024 + j];
    float go = gx[1536 + j] + g1[1536 + j] + g2[1536 + j] + b_ih[1536 + j] + b_hh[1536 + j];

    float m = 1.0f - done[n];
    float c = g_c[idx] * m;
    float cn = sigm(gf) * c + sigm(gi) * tanhf(gg);
    float hn = sigm(go) * tanhf(cn);
    g_c[idx] = cn;
    g_h[idx] = hn;
    g_hidden[(size_t)n * 512 + j] = hn;
}

// ---------------------------------------------------------------------------
__global__ void __launch_bounds__(256) head_kernel(const float* __restrict__ Wa,
                                                   const float* __restrict__ ba,
                                                   const float* __restrict__ Wc,
                                                   const float* __restrict__ bc,
                                                   float* __restrict__ out) {
    int warp = threadIdx.x / 32, lane = threadIdx.x % 32;
    int n = blockIdx.x * 8 + warp;
    float h[16];
    #pragma unroll
    for (int i = 0; i < 16; i++) h[i] = g_hidden[(size_t)n * 512 + i * 32 + lane];
    for (int j = 0; j < 19; j++) {
        const float* w = (j < 18) ? (Wa + j * 512) : Wc;
        float s = 0.f;
        #pragma unroll
        for (int i = 0; i < 16; i++) s += h[i] * w[i * 32 + lane];
        #pragma unroll
        for (int o = 16; o; o >>= 1) s += __shfl_xor_sync(0xffffffffu, s, o);
        if (lane == 0) out[n * 19 + j] = s + ((j < 18) ? ba[j] : bc[0]);
    }
}

__global__ void init_state_kernel(const float* __restrict__ h0, const float* __restrict__ c0) {
    int idx = blockIdx.x * blockDim.x + threadIdx.x;
    if (idx < 64 * 512) { g_h[idx] = h0[idx]; g_c[idx] = c0[idx]; }
}

__global__ void copy_out_kernel(float* __restrict__ out) {
    int idx = blockIdx.x * blockDim.x + threadIdx.x;
    if (idx < 64 * 512) {
        out[19456 + idx] = g_h[idx];
        out[19456 + 32768 + idx] = g_c[idx];
    }
}

// ---------------------------------------------------------------------------
extern "C" void kernel_launch(void* const* d_in, const int* in_sizes, int n_in,
                              void* d_out, int out_size) {
    const float* x    = (const float*)d_in[0];
    const float* done = (const float*)d_in[1];
    const float* h0   = (const float*)d_in[2];
    const float* c0   = (const float*)d_in[3];
    const float* w1   = (const float*)d_in[4];
    const float* b1   = (const float*)d_in[5];
    const float* w2   = (const float*)d_in[6];
    const float* b2   = (const float*)d_in[7];
    const float* w3   = (const float*)d_in[8];
    const float* b3   = (const float*)d_in[9];
    const float* w4   = (const float*)d_in[10];
    const float* b4   = (const float*)d_in[11];
    const float* W_ih = (const float*)d_in[12];
    const float* W_hh = (const float*)d_in[13];
    const float* b_ih = (const float*)d_in[14];
    const float* b_hh = (const float*)d_in[15];
    const float* Wa   = (const float*)d_in[16];
    const float* ba   = (const float*)d_in[17];
    const float* Wc   = (const float*)d_in[18];
    const float* bc   = (const float*)d_in[19];
    float* out = (float*)d_out;

    const int SM1 = (11264 + 3584) * 4;   // 59392
    const int SM2 = (19712 + 28672) * 4;  // 193536
    const int SM3 = (14784 + 32768) * 4;  // 190208
    const int SM4 = (8448 + 49152) * 4;   // 230400
    cudaFuncSetAttribute(conv1_kernel, cudaFuncAttributeMaxDynamicSharedMemorySize, SM1);
    cudaFuncSetAttribute(conv2_kernel, cudaFuncAttributeMaxDynamicSharedMemorySize, SM2);
    cudaFuncSetAttribute(conv3_kernel, cudaFuncAttributeMaxDynamicSharedMemorySize, SM3);
    cudaFuncSetAttribute(conv4_kernel, cudaFuncAttributeMaxDynamicSharedMemorySize, SM4);

    init_state_kernel<<<128, 256>>>(h0, c0);

    conv1_kernel<<<dim3(NSAMP, 3), 320, SM1>>>(x, w1, b1);
    conv2_kernel<<<dim3(NSAMP, 4), 320, SM2>>>(w2, b2);
    conv3_kernel<<<NSAMP, 512, SM3>>>(w3, b3);
    conv4_kernel<<<NSAMP, 512, SM4>>>(w4, b4);

    gemm_gx_kernel<<<dim3(2048 / 64, 1024 / 64, 1), 256>>>(W_ih);

    for (int t = 0; t < 16; t++) {
        gemm_hh_kernel<<<dim3(2048 / 32, 1, 2), 256>>>(W_hh, done, t);
        lstm_update_kernel<<<128, 256>>>(b_ih, b_hh, done, t);
    }

    head_kernel<<<NSAMP / 8, 256>>>(Wa, ba, Wc, bc, out);
    copy_out_kernel<<<128, 256>>>(out);
}

// round 14
// speedup vs baseline: 1.0447x; 1.0126x over previous
#include <cuda_runtime.h>
#include <cuda_bf16.h>
#include <math.h>

// ---------------------------------------------------------------------------
//  x (1024,4,84,84) -> conv1 5x5 p2 -> pool -> relu : a1 (1024,32,42,42)
//  conv2 5x5 p1 -> pool -> relu : a2 (1024,32,20,20)
//  conv3 4x4 p1 -> pool -> relu : a3 (1024,64,9,9)
//  conv4 3x3 p1 -> pool -> relu -> flatten : feat (1024,1024)
//  LSTM T=16 B=64 H=512 ; heads -> out (1024,19) + hT + cT
//
//  Scalar fp32 convs: 4 output channels per thread (16 named accumulators),
//  tap-major weights transposed INLINE during smem staging (no separate
//  transpose kernels / scratch), row-streaming input (KW+1 floats live).
// ---------------------------------------------------------------------------

#define NSAMP 1024

__device__ float g_a1[NSAMP * 32 * 42 * 42];
__device__ float g_a2[NSAMP * 32 * 20 * 20];
__device__ float g_a3[NSAMP * 64 * 9 * 9];
__device__ float g_feat[NSAMP * 1024];
__device__ float g_gx[NSAMP * 2048];
__device__ float g_ghh[2 * 64 * 2048];
__device__ float g_h[64 * 512];
__device__ float g_c[64 * 512];
__device__ float g_hidden[NSAMP * 512];

// 16 named accumulators: a[j][d] = oc j, d in {dy0-L, dy0-R, dy1-L, dy1-R}
struct Acc16 {
    float a00, a01, a02, a03;
    float a10, a11, a12, a13;
    float a20, a21, a22, a23;
    float a30, a31, a32, a33;
};

// Row-streaming conv core for one input channel.
// sp: smem ptr at (2py, 2px); wq: float4 base for this channel/q-group
// (stride NOCQ float4s per tap).
template <int KH, int KW, int NOCQ>
__device__ __forceinline__ void conv_rows(const float* __restrict__ sp,
                                          const float4* __restrict__ wq,
                                          int TW, Acc16& A) {
    #pragma unroll
    for (int r = 0; r < KH + 1; r++) {
        float v[KW + 1];
        #pragma unroll
        for (int c = 0; c < KW + 1; c += 2) {
            float2 t = *(const float2*)(sp + r * TW + c);
            v[c] = t.x;
            if (c + 1 < KW + 1) v[c + 1] = t.y;
        }
        if (r < KH) {   // dy = 0 pass: ky = r
            #pragma unroll
            for (int kx = 0; kx < KW; kx++) {
                float4 w4 = wq[(r * KW + kx) * NOCQ];
                A.a00 += w4.x * v[kx]; A.a01 += w4.x * v[kx + 1];
                A.a10 += w4.y * v[kx]; A.a11 += w4.y * v[kx + 1];
                A.a20 += w4.z * v[kx]; A.a21 += w4.z * v[kx + 1];
                A.a30 += w4.w * v[kx]; A.a31 += w4.w * v[kx + 1];
            }
        }
        if (r >= 1) {   // dy = 1 pass: ky = r - 1
            #pragma unroll
            for (int kx = 0; kx < KW; kx++) {
                float4 w4 = wq[((r - 1) * KW + kx) * NOCQ];
                A.a02 += w4.x * v[kx]; A.a03 += w4.x * v[kx + 1];
                A.a12 += w4.y * v[kx]; A.a13 += w4.y * v[kx + 1];
                A.a22 += w4.z * v[kx]; A.a23 += w4.z * v[kx + 1];
                A.a32 += w4.w * v[kx]; A.a33 += w4.w * v[kx + 1];
            }
        }
    }
}

#define POOL4_STORE(BIAS)                                                      \
    {                                                                          \
        float m0 = fmaxf(fmaxf(A.a00, A.a01), fmaxf(A.a02, A.a03)) + (BIAS)[oc0];     \
        float m1 = fmaxf(fmaxf(A.a10, A.a11), fmaxf(A.a12, A.a13)) + (BIAS)[oc0 + 1]; \
        float m2 = fmaxf(fmaxf(A.a20, A.a21), fmaxf(A.a22, A.a23)) + (BIAS)[oc0 + 2]; \
        float m3 = fmaxf(fmaxf(A.a30, A.a31), fmaxf(A.a32, A.a33)) + (BIAS)[oc0 + 3]; \
        dst_store(0, fmaxf(m0, 0.f));                                          \
        dst_store(1, fmaxf(m1, 0.f));                                          \
        dst_store(2, fmaxf(m2, 0.f));                                          \
        dst_store(3, fmaxf(m3, 0.f));                                          \
    }

// ---------------------------------------------------------------------------
// conv1: grid (1024, 3 strips of 14 pooled rows), 320 thr, 2 blk/SM.
// smem: 4*32*88 + 4*25*32 = 11264 + 3200 floats = 57856 B
// ---------------------------------------------------------------------------
__global__ void __launch_bounds__(320, 2) conv1_kernel(const float* __restrict__ x,
                                                       const float* __restrict__ w,
                                                       const float* __restrict__ bias) {
    extern __shared__ float sm[];
    float* s_in = sm;                 // 11264
    float* s_w  = sm + 11264;         // 3200: [(ic*25+tap)*32 + oc]
    const int n = blockIdx.x;
    const int strip = blockIdx.y;

    for (int i = threadIdx.x; i < 11264; i += blockDim.x) {
        int ic = i / 2816;
        int rem = i % 2816;
        int r = rem / 88, c = rem % 88;
        int y = 28 * strip - 2 + r, xx = c - 2;
        float v = 0.f;
        if ((unsigned)y < 84u && (unsigned)xx < 84u)
            v = x[((n * 4 + ic) * 84 + y) * 84 + xx];
        s_in[i] = v;
    }
    for (int i = threadIdx.x; i < 3200; i += blockDim.x) {
        int oc = i % 32;
        int tap = (i / 32) % 25;
        int ic = i / 800;
        s_w[i] = w[(oc * 4 + ic) * 25 + tap];
    }
    __syncthreads();

    for (int p = threadIdx.x; p < 8 * 588; p += blockDim.x) {
        int q = p / 588;
        int rem = p % 588;
        int py = rem / 42, px = rem % 42;
        int oc0 = 4 * q;
        Acc16 A = {};
        #pragma unroll
        for (int ic = 0; ic < 4; ic++) {
            const float* sp = s_in + ic * 2816 + (2 * py) * 88 + 2 * px;
            const float4* wq = ((const float4*)s_w) + ic * 25 * 8 + q;
            conv_rows<5, 5, 8>(sp, wq, 88, A);
        }
        int pyg = 14 * strip + py;
        #define dst_store(J, V) g_a1[((n * 32 + oc0 + (J)) * 42 + pyg) * 42 + px] = (V)
        POOL4_STORE(bias)
        #undef dst_store
    }
}

// ---------------------------------------------------------------------------
// conv2: grid (1024, 4 strips of 5 pooled rows), 320 thr.
// smem: 32*14*44 + 32*25*32 = 19712 + 25600 floats = 181248 B
// ---------------------------------------------------------------------------
__global__ void __launch_bounds__(320) conv2_kernel(const float* __restrict__ w,
                                                    const float* __restrict__ bias) {
    extern __shared__ float sm[];
    float* s_in = sm;                 // 19712
    float* s_w  = sm + 19712;         // 25600: [(ic*25+tap)*32 + oc]
    const int n = blockIdx.x;
    const int py0 = 5 * blockIdx.y;

    for (int i = threadIdx.x; i < 19712; i += blockDim.x) {
        int ic = i / 616;
        int rem = i % 616;
        int rr = rem / 44, cc = rem % 44;
        int y = 2 * py0 - 1 + rr;
        int xx = cc - 1;
        float v = 0.f;
        if ((unsigned)y < 42u && (unsigned)xx < 42u)
            v = g_a1[((n * 32 + ic) * 42 + y) * 42 + xx];
        s_in[i] = v;
    }
    for (int i = threadIdx.x; i < 25600; i += blockDim.x) {
        int oc = i % 32;
        int tap = (i / 32) % 25;
        int ic = i / 800;
        s_w[i] = w[(oc * 32 + ic) * 25 + tap];
    }
    __syncthreads();

    for (int p = threadIdx.x; p < 8 * 100; p += blockDim.x) {
        int q = p / 100;
        int rem = p % 100;
        int lpy = rem / 20, px = rem % 20;
        int oc0 = 4 * q;
        Acc16 A = {};
        #pragma unroll 1
        for (int ic = 0; ic < 32; ic++) {
            const float* sp = s_in + ic * 616 + (2 * lpy) * 44 + 2 * px;
            const float4* wq = ((const float4*)s_w) + ic * 25 * 8 + q;
            conv_rows<5, 5, 8>(sp, wq, 44, A);
        }
        int py = py0 + lpy;
        #define dst_store(J, V) g_a2[((n * 32 + oc0 + (J)) * 20 + py) * 20 + px] = (V)
        POOL4_STORE(bias)
        #undef dst_store
    }
}

// ---------------------------------------------------------------------------
// conv3: grid (1024), 512 thr. input stride padded 21->22.
// smem: 32*21*22 + 32*16*64 = 14784 + 32768 floats = 190208 B
// ---------------------------------------------------------------------------
__global__ void __launch_bounds__(512) conv3_kernel(const float* __restrict__ w,
                                                    const float* __restrict__ bias) {
    extern __shared__ float sm[];
    float* s_in = sm;            // 14784
    float* s_w  = sm + 14784;    // 32768: [(ic*16+tap)*64 + oc]
    const int n = blockIdx.x;

    for (int i = threadIdx.x; i < 14784; i += blockDim.x) {
        int ic = i / 462;
        int rem = i % 462;
        int r = rem / 22, c = rem % 22;
        float v = 0.f;
        if (c < 21) {
            int y = r - 1, xx = c - 1;
            if ((unsigned)y < 20u && (unsigned)xx < 20u)
                v = g_a2[((n * 32 + ic) * 20 + y) * 20 + xx];
        }
        s_in[i] = v;
    }
    for (int i = threadIdx.x; i < 32768; i += blockDim.x) {
        int oc = i % 64;
        int tap = (i / 64) % 16;
        int ic = i / 1024;
        s_w[i] = w[(oc * 32 + ic) * 16 + tap];
    }
    __syncthreads();

    for (int p = threadIdx.x; p < 16 * 81; p += blockDim.x) {
        int q = p / 81;
        int rem = p % 81;
        int py = rem / 9, px = rem % 9;
        int oc0 = 4 * q;
        Acc16 A = {};
        #pragma unroll 1
        for (int ic = 0; ic < 32; ic++) {
            const float* sp = s_in + ic * 462 + (2 * py) * 22 + 2 * px;
            const float4* wq = ((const float4*)s_w) + ic * 16 * 16 + q;
            conv_rows<4, 4, 16>(sp, wq, 22, A);
        }
        #define dst_store(J, V) g_a3[((n * 64 + oc0 + (J)) * 9 + py) * 9 + px] = (V)
        POOL4_STORE(bias)
        #undef dst_store
    }
}

// ---------------------------------------------------------------------------
// conv4: grid (1024), 256 thr (1 task each: 16 quads x 16 px).
// smem: 64*11*12 + 64*9*64 = 8448 + 36864 floats = 181248 B
// ---------------------------------------------------------------------------
__global__ void __launch_bounds__(256) conv4_kernel(const float* __restrict__ w,
                                                    const float* __restrict__ bias) {
    extern __shared__ float sm[];
    float* s_in = sm;                 // 8448
    float* s_w  = sm + 8448;          // 36864: [(ic*9+tap)*64 + oc]
    const int n = blockIdx.x;

    for (int i = threadIdx.x; i < 8448; i += blockDim.x) {
        int ic = i / 132;
        int rem = i % 132;
        int r = rem / 12, c = rem % 12;
        int y = r - 1, xx = c - 1;
        float v = 0.f;
        if ((unsigned)y < 9u && (unsigned)xx < 9u)
            v = g_a3[((n * 64 + ic) * 9 + y) * 9 + xx];
        s_in[i] = v;
    }
    for (int i = threadIdx.x; i < 36864; i += blockDim.x) {
        int oc = i % 64;
        int tap = (i / 64) % 9;
        int ic = i / 576;
        s_w[i] = w[(oc * 64 + ic) * 9 + tap];
    }
    __syncthreads();

    {
        int p = threadIdx.x;
        int q = p / 16;
        int rem = p % 16;
        int py = rem / 4, px = rem % 4;
        int oc0 = 4 * q;
        Acc16 A = {};
        #pragma unroll 1
        for (int ic = 0; ic < 64; ic++) {
            const float* sp = s_in + ic * 132 + (2 * py) * 12 + 2 * px;
            const float4* wq = ((const float4*)s_w) + ic * 9 * 16 + q;
            conv_rows<3, 3, 16>(sp, wq, 12, A);
        }
        #define dst_store(J, V) g_feat[n * 1024 + (oc0 + (J)) * 16 + py * 4 + px] = (V)
        POOL4_STORE(bias)
        #undef dst_store
    }
}

// ---------------------------------------------------------------------------
// GEMM  C[M,N] = A[M,K] @ B[N,K]^T
// ---------------------------------------------------------------------------
template <int BM, int BN, int BK, int TM, int TN, bool MASK, bool SPLITK>
__device__ __forceinline__ void gemm_body(const float* __restrict__ A,
                                          const float* __restrict__ B,
                                          float* __restrict__ C,
                                          int M, int N, int Kd,
                                          const float* __restrict__ dvec) {
    __shared__ float As[BK][BM + 4];
    __shared__ float Bs[BK][BN + 4];
    constexpr int NTr = (BM / TM) * (BN / TN);
    const int tid = threadIdx.x;
    const int tx = tid % (BN / TN);
    const int ty = tid / (BN / TN);
    const int m0 = blockIdx.y * BM;
    const int n0 = blockIdx.x * BN;
    int kBeg = 0, kEnd = Kd;
    if (SPLITK) {
        int kc = Kd / gridDim.z;
        kBeg = blockIdx.z * kc;
        kEnd = kBeg + kc;
        C += (size_t)blockIdx.z * M * N;
    }
    float acc[TM][TN];
    #pragma unroll
    for (int i = 0; i < TM; i++)
        #pragma unroll
        for (int j = 0; j < TN; j++) acc[i][j] = 0.f;

    for (int kk = kBeg; kk < kEnd; kk += BK) {
        for (int i = tid; i < BM * BK; i += NTr) {
            int r = i / BK, c = i % BK;
            float v = A[(m0 + r) * Kd + kk + c];
            if (MASK) v *= (1.0f - dvec[m0 + r]);
            As[c][r] = v;
        }
        for (int i = tid; i < BN * BK; i += NTr) {
            int r = i / BK, c = i % BK;
            Bs[c][r] = B[(n0 + r) * Kd + kk + c];
        }
        __syncthreads();
        #pragma unroll
        for (int k = 0; k < BK; k++) {
            float a[TM], b[TN];
            #pragma unroll
            for (int i = 0; i < TM; i++) a[i] = As[k][ty * TM + i];
            #pragma unroll
            for (int j = 0; j < TN; j++) b[j] = Bs[k][tx * TN + j];
            #pragma unroll
            for (int i = 0; i < TM; i++)
                #pragma unroll
                for (int j = 0; j < TN; j++) acc[i][j] += a[i] * b[j];
        }
        __syncthreads();
    }
    #pragma unroll
    for (int i = 0; i < TM; i++)
        #pragma unroll
        for (int j = 0; j < TN; j++)
            C[(size_t)(m0 + ty * TM + i) * N + n0 + tx * TN + j] = acc[i][j];
}

__global__ void __launch_bounds__(256) gemm_gx_kernel(const float* __restrict__ W_ih) {
    gemm_body<64, 64, 16, 4, 4, false, false>(g_feat, W_ih, g_gx, 1024, 2048, 1024, nullptr);
}

__global__ void __launch_bounds__(256) gemm_hh_kernel(const float* __restrict__ W_hh,
                                                      const float* __restrict__ done, int t) {
    gemm_body<64, 32, 16, 4, 2, true, true>(g_h, W_hh, g_ghh, 64, 2048, 512, done + t * 64);
}

// ---------------------------------------------------------------------------
__device__ __forceinline__ float sigm(float x) { return 1.f / (1.f + expf(-x)); }

__global__ void lstm_update_kernel(const float* __restrict__ b_ih,
                                   const float* __restrict__ b_hh,
                                   const float* __restrict__ done, int t) {
    int idx = blockIdx.x * blockDim.x + threadIdx.x;
    if (idx >= 64 * 512) return;
    int b = idx / 512, j = idx % 512;
    int n = t * 64 + b;
    const float* gx = g_gx + (size_t)n * 2048;
    const float* g1 = g_ghh + (size_t)b * 2048;
    const float* g2 = g_ghh + 64 * 2048 + (size_t)b * 2048;

    float gi = gx[j]        + g1[j]        + g2[j]        + b_ih[j]        + b_hh[j];
    float gf = gx[512 + j]  + g1[512 + j]  + g2[512 + j]  + b_ih[512 + j]  + b_hh[512 + j];
    float gg = gx[1024 + j] + g1[1024 + j] + g2[1024 + j] + b_ih[1024 + j] + b_hh[1024 + j];
    float go = gx[1536 + j] + g1[1536 + j] + g2[1536 + j] + b_ih[1536 + j] + b_hh[1536 + j];

    float m = 1.0f - done[n];
    float c = g_c[idx] * m;
    float cn = sigm(gf) * c + sigm(gi) * tanhf(gg);
    float hn = sigm(go) * tanhf(cn);
    g_c[idx] = cn;
    g_h[idx] = hn;
    g_hidden[(size_t)n * 512 + j] = hn;
}

// ---------------------------------------------------------------------------
__global__ void __launch_bounds__(256) head_kernel(const float* __restrict__ Wa,
                                                   const float* __restrict__ ba,
                                                   const float* __restrict__ Wc,
                                                   const float* __restrict__ bc,
                                                   float* __restrict__ out) {
    int warp = threadIdx.x / 32, lane = threadIdx.x % 32;
    int n = blockIdx.x * 8 + warp;
    float h[16];
    #pragma unroll
    for (int i = 0; i < 16; i++) h[i] = g_hidden[(size_t)n * 512 + i * 32 + lane];
    for (int j = 0; j < 19; j++) {
        const float* w = (j < 18) ? (Wa + j * 512) : Wc;
        float s = 0.f;
        #pragma unroll
        for (int i = 0; i < 16; i++) s += h[i] * w[i * 32 + lane];
        #pragma unroll
        for (int o = 16; o; o >>= 1) s += __shfl_xor_sync(0xffffffffu, s, o);
        if (lane == 0) out[n * 19 + j] = s + ((j < 18) ? ba[j] : bc[0]);
    }
}

__global__ void init_state_kernel(const float* __restrict__ h0, const float* __restrict__ c0) {
    int idx = blockIdx.x * blockDim.x + threadIdx.x;
    if (idx < 64 * 512) { g_h[idx] = h0[idx]; g_c[idx] = c0[idx]; }
}

__global__ void copy_out_kernel(float* __restrict__ out) {
    int idx = blockIdx.x * blockDim.x + threadIdx.x;
    if (idx < 64 * 512) {
        out[19456 + idx] = g_h[idx];
        out[19456 + 32768 + idx] = g_c[idx];
    }
}

// ---------------------------------------------------------------------------
extern "C" void kernel_launch(void* const* d_in, const int* in_sizes, int n_in,
                              void* d_out, int out_size) {
    const float* x    = (const float*)d_in[0];
    const float* done = (const float*)d_in[1];
    const float* h0   = (const float*)d_in[2];
    const float* c0   = (const float*)d_in[3];
    const float* w1   = (const float*)d_in[4];
    const float* b1   = (const float*)d_in[5];
    const float* w2   = (const float*)d_in[6];
    const float* b2   = (const float*)d_in[7];
    const float* w3   = (const float*)d_in[8];
    const float* b3   = (const float*)d_in[9];
    const float* w4   = (const float*)d_in[10];
    const float* b4   = (const float*)d_in[11];
    const float* W_ih = (const float*)d_in[12];
    const float* W_hh = (const float*)d_in[13];
    const float* b_ih = (const float*)d_in[14];
    const float* b_hh = (const float*)d_in[15];
    const float* Wa   = (const float*)d_in[16];
    const float* ba   = (const float*)d_in[17];
    const float* Wc   = (const float*)d_in[18];
    const float* bc   = (const float*)d_in[19];
    float* out = (float*)d_out;

    const int SM1 = (11264 + 3200) * 4;   // 57856
    const int SM2 = (19712 + 25600) * 4;  // 181248
    const int SM3 = (14784 + 32768) * 4;  // 190208
    const int SM4 = (8448 + 36864) * 4;   // 181248
    cudaFuncSetAttribute(conv1_kernel, cudaFuncAttributeMaxDynamicSharedMemorySize, SM1);
    cudaFuncSetAttribute(conv2_kernel, cudaFuncAttributeMaxDynamicSharedMemorySize, SM2);
    cudaFuncSetAttribute(conv3_kernel, cudaFuncAttributeMaxDynamicSharedMemorySize, SM3);
    cudaFuncSetAttribute(conv4_kernel, cudaFuncAttributeMaxDynamicSharedMemorySize, SM4);

    init_state_kernel<<<128, 256>>>(h0, c0);

    conv1_kernel<<<dim3(NSAMP, 3), 320, SM1>>>(x, w1, b1);
    conv2_kernel<<<dim3(NSAMP, 4), 320, SM2>>>(w2, b2);
    conv3_kernel<<<NSAMP, 512, SM3>>>(w3, b3);
    conv4_kernel<<<NSAMP, 256, SM4>>>(w4, b4);

    gemm_gx_kernel<<<dim3(2048 / 64, 1024 / 64, 1), 256>>>(W_ih);

    for (int t = 0; t < 16; t++) {
        gemm_hh_kernel<<<dim3(2048 / 32, 1, 2), 256>>>(W_hh, done, t);
        lstm_update_kernel<<<128, 256>>>(b_ih, b_hh, done, t);
    }

    head_kernel<<<NSAMP / 8, 256>>>(Wa, ba, Wc, bc, out);
    copy_out_kernel<<<128, 256>>>(out);
}

// round 16
// speedup vs baseline: 1.2341x; 1.1812x over previous
#include <cuda_runtime.h>
#include <cuda_bf16.h>
#include <math.h>

// ---------------------------------------------------------------------------
//  x (1024,4,84,84) -> conv1 5x5 p2 -> pool -> relu : a1 (1024,32,42,42)
//  conv2 5x5 p1 -> pool -> relu : a2 (1024,32,20,20)
//  conv3 4x4 p1 -> pool -> relu : a3 (1024,64,9,9)
//  conv4 3x3 p1 -> pool -> relu -> flatten : feat (1024,1024)
//  LSTM T=16 B=64 H=512 ; heads -> out (1024,19) + hT + cT
//
//  Scalar fp32 convs: 4 ocs/thread (16 named accumulators), tap-major
//  weights transposed inline during staging with COALESCED gmem reads and
//  padded smem stride (NOC+4) to kill scatter bank conflicts.
// ---------------------------------------------------------------------------

#define NSAMP 1024

__device__ float g_a1[NSAMP * 32 * 42 * 42];
__device__ float g_a2[NSAMP * 32 * 20 * 20];
__device__ float g_a3[NSAMP * 64 * 9 * 9];
__device__ float g_feat[NSAMP * 1024];
__device__ float g_gx[NSAMP * 2048];
__device__ float g_ghh[2 * 64 * 2048];
__device__ float g_h[64 * 512];
__device__ float g_c[64 * 512];
__device__ float g_hidden[NSAMP * 512];

// 16 named accumulators: a[j][d] = oc j, d in {dy0-L, dy0-R, dy1-L, dy1-R}
struct Acc16 {
    float a00, a01, a02, a03;
    float a10, a11, a12, a13;
    float a20, a21, a22, a23;
    float a30, a31, a32, a33;
};

// Row-streaming conv core for one input channel.
// sp: smem ptr at (2py, 2px); wq: float4 base for this channel/q-group;
// STRQ = padded weight stride per tap, in float4s.
template <int KH, int KW, int STRQ>
__device__ __forceinline__ void conv_rows(const float* __restrict__ sp,
                                          const float4* __restrict__ wq,
                                          int TW, Acc16& A) {
    #pragma unroll
    for (int r = 0; r < KH + 1; r++) {
        float v[KW + 1];
        #pragma unroll
        for (int c = 0; c < KW + 1; c += 2) {
            float2 t = *(const float2*)(sp + r * TW + c);
            v[c] = t.x;
            if (c + 1 < KW + 1) v[c + 1] = t.y;
        }
        if (r < KH) {   // dy = 0 pass: ky = r
            #pragma unroll
            for (int kx = 0; kx < KW; kx++) {
                float4 w4 = wq[(r * KW + kx) * STRQ];
                A.a00 += w4.x * v[kx]; A.a01 += w4.x * v[kx + 1];
                A.a10 += w4.y * v[kx]; A.a11 += w4.y * v[kx + 1];
                A.a20 += w4.z * v[kx]; A.a21 += w4.z * v[kx + 1];
                A.a30 += w4.w * v[kx]; A.a31 += w4.w * v[kx + 1];
            }
        }
        if (r >= 1) {   // dy = 1 pass: ky = r - 1
            #pragma unroll
            for (int kx = 0; kx < KW; kx++) {
                float4 w4 = wq[((r - 1) * KW + kx) * STRQ];
                A.a02 += w4.x * v[kx]; A.a03 += w4.x * v[kx + 1];
                A.a12 += w4.y * v[kx]; A.a13 += w4.y * v[kx + 1];
                A.a22 += w4.z * v[kx]; A.a23 += w4.z * v[kx + 1];
                A.a32 += w4.w * v[kx]; A.a33 += w4.w * v[kx + 1];
            }
        }
    }
}

#define POOL4_STORE(BIAS)                                                      \
    {                                                                          \
        float m0 = fmaxf(fmaxf(A.a00, A.a01), fmaxf(A.a02, A.a03)) + (BIAS)[oc0];     \
        float m1 = fmaxf(fmaxf(A.a10, A.a11), fmaxf(A.a12, A.a13)) + (BIAS)[oc0 + 1]; \
        float m2 = fmaxf(fmaxf(A.a20, A.a21), fmaxf(A.a22, A.a23)) + (BIAS)[oc0 + 2]; \
        float m3 = fmaxf(fmaxf(A.a30, A.a31), fmaxf(A.a32, A.a33)) + (BIAS)[oc0 + 3]; \
        dst_store(0, fmaxf(m0, 0.f));                                          \
        dst_store(1, fmaxf(m1, 0.f));                                          \
        dst_store(2, fmaxf(m2, 0.f));                                          \
        dst_store(3, fmaxf(m3, 0.f));                                          \
    }

// Coalesced weight staging: read w linearly (lane-fast = tap), scatter into
// padded tap-major smem layout s_w[(ic*TAPS+tap)*STR + oc].
#define STAGE_W(W, SW, NOC, ICR, TAPS, STR)                                    \
    for (int i = threadIdx.x; i < (NOC) * (ICR) * (TAPS); i += blockDim.x) {   \
        int tap = i % (TAPS);                                                  \
        int ic = (i / (TAPS)) % (ICR);                                         \
        int oc = i / ((TAPS) * (ICR));                                         \
        (SW)[(ic * (TAPS) + tap) * (STR) + oc] = (W)[i];                       \
    }

// ---------------------------------------------------------------------------
// conv1: grid (1024, 3 strips of 14 pooled rows), 320 thr, 2 blk/SM.
// smem: 4*32*88 + 4*25*36 = 11264 + 3600 floats = 59456 B
// ---------------------------------------------------------------------------
__global__ void __launch_bounds__(320, 2) conv1_kernel(const float* __restrict__ x,
                                                       const float* __restrict__ w,
                                                       const float* __restrict__ bias) {
    extern __shared__ float sm[];
    float* s_in = sm;                 // 11264
    float* s_w  = sm + 11264;         // 3600: [(ic*25+tap)*36 + oc]
    const int n = blockIdx.x;
    const int strip = blockIdx.y;

    for (int i = threadIdx.x; i < 11264; i += blockDim.x) {
        int ic = i / 2816;
        int rem = i % 2816;
        int r = rem / 88, c = rem % 88;
        int y = 28 * strip - 2 + r, xx = c - 2;
        float v = 0.f;
        if ((unsigned)y < 84u && (unsigned)xx < 84u)
            v = x[((n * 4 + ic) * 84 + y) * 84 + xx];
        s_in[i] = v;
    }
    STAGE_W(w, s_w, 32, 4, 25, 36)
    __syncthreads();

    for (int p = threadIdx.x; p < 8 * 588; p += blockDim.x) {
        int q = p / 588;
        int rem = p % 588;
        int py = rem / 42, px = rem % 42;
        int oc0 = 4 * q;
        Acc16 A = {};
        #pragma unroll
        for (int ic = 0; ic < 4; ic++) {
            const float* sp = s_in + ic * 2816 + (2 * py) * 88 + 2 * px;
            const float4* wq = ((const float4*)s_w) + ic * 25 * 9 + q;
            conv_rows<5, 5, 9>(sp, wq, 88, A);
        }
        int pyg = 14 * strip + py;
        #define dst_store(J, V) g_a1[((n * 32 + oc0 + (J)) * 42 + pyg) * 42 + px] = (V)
        POOL4_STORE(bias)
        #undef dst_store
    }
}

// ---------------------------------------------------------------------------
// conv2: grid (1024, 4 strips of 5 pooled rows), 512 thr.
// smem: 32*14*44 + 32*25*36 = 19712 + 28800 floats = 194048 B
// ---------------------------------------------------------------------------
__global__ void __launch_bounds__(512) conv2_kernel(const float* __restrict__ w,
                                                    const float* __restrict__ bias) {
    extern __shared__ float sm[];
    float* s_in = sm;                 // 19712
    float* s_w  = sm + 19712;         // 28800: [(ic*25+tap)*36 + oc]
    const int n = blockIdx.x;
    const int py0 = 5 * blockIdx.y;

    for (int i = threadIdx.x; i < 19712; i += blockDim.x) {
        int ic = i / 616;
        int rem = i % 616;
        int rr = rem / 44, cc = rem % 44;
        int y = 2 * py0 - 1 + rr;
        int xx = cc - 1;
        float v = 0.f;
        if ((unsigned)y < 42u && (unsigned)xx < 42u)
            v = g_a1[((n * 32 + ic) * 42 + y) * 42 + xx];
        s_in[i] = v;
    }
    STAGE_W(w, s_w, 32, 32, 25, 36)
    __syncthreads();

    for (int p = threadIdx.x; p < 8 * 100; p += blockDim.x) {
        int q = p / 100;
        int rem = p % 100;
        int lpy = rem / 20, px = rem % 20;
        int oc0 = 4 * q;
        Acc16 A = {};
        #pragma unroll 1
        for (int ic = 0; ic < 32; ic++) {
            const float* sp = s_in + ic * 616 + (2 * lpy) * 44 + 2 * px;
            const float4* wq = ((const float4*)s_w) + ic * 25 * 9 + q;
            conv_rows<5, 5, 9>(sp, wq, 44, A);
        }
        int py = py0 + lpy;
        #define dst_store(J, V) g_a2[((n * 32 + oc0 + (J)) * 20 + py) * 20 + px] = (V)
        POOL4_STORE(bias)
        #undef dst_store
    }
}

// ---------------------------------------------------------------------------
// conv3: grid (1024), 512 thr. input stride padded 21->22.
// smem: 32*21*22 + 32*16*68 = 14784 + 34816 floats = 198400 B
// ---------------------------------------------------------------------------
__global__ void __launch_bounds__(512) conv3_kernel(const float* __restrict__ w,
                                                    const float* __restrict__ bias) {
    extern __shared__ float sm[];
    float* s_in = sm;            // 14784
    float* s_w  = sm + 14784;    // 34816: [(ic*16+tap)*68 + oc]
    const int n = blockIdx.x;

    for (int i = threadIdx.x; i < 14784; i += blockDim.x) {
        int ic = i / 462;
        int rem = i % 462;
        int r = rem / 22, c = rem % 22;
        float v = 0.f;
        if (c < 21) {
            int y = r - 1, xx = c - 1;
            if ((unsigned)y < 20u && (unsigned)xx < 20u)
                v = g_a2[((n * 32 + ic) * 20 + y) * 20 + xx];
        }
        s_in[i] = v;
    }
    STAGE_W(w, s_w, 64, 32, 16, 68)
    __syncthreads();

    for (int p = threadIdx.x; p < 16 * 81; p += blockDim.x) {
        int q = p / 81;
        int rem = p % 81;
        int py = rem / 9, px = rem % 9;
        int oc0 = 4 * q;
        Acc16 A = {};
        #pragma unroll 1
        for (int ic = 0; ic < 32; ic++) {
            const float* sp = s_in + ic * 462 + (2 * py) * 22 + 2 * px;
            const float4* wq = ((const float4*)s_w) + ic * 16 * 17 + q;
            conv_rows<4, 4, 17>(sp, wq, 22, A);
        }
        #define dst_store(J, V) g_a3[((n * 64 + oc0 + (J)) * 9 + py) * 9 + px] = (V)
        POOL4_STORE(bias)
        #undef dst_store
    }
}

// ---------------------------------------------------------------------------
// conv4: grid (1024), 256 thr (1 task each: 16 quads x 16 px).
// smem: 64*11*12 + 64*9*68 = 8448 + 39168 floats = 190464 B
// ---------------------------------------------------------------------------
__global__ void __launch_bounds__(256) conv4_kernel(const float* __restrict__ w,
                                                    const float* __restrict__ bias) {
    extern __shared__ float sm[];
    float* s_in = sm;                 // 8448
    float* s_w  = sm + 8448;          // 39168: [(ic*9+tap)*68 + oc]
    const int n = blockIdx.x;

    for (int i = threadIdx.x; i < 8448; i += blockDim.x) {
        int ic = i / 132;
        int rem = i % 132;
        int r = rem / 12, c = rem % 12;
        int y = r - 1, xx = c - 1;
        float v = 0.f;
        if ((unsigned)y < 9u && (unsigned)xx < 9u)
            v = g_a3[((n * 64 + ic) * 9 + y) * 9 + xx];
        s_in[i] = v;
    }
    STAGE_W(w, s_w, 64, 64, 9, 68)
    __syncthreads();

    {
        int p = threadIdx.x;
        int q = p / 16;
        int rem = p % 16;
        int py = rem / 4, px = rem % 4;
        int oc0 = 4 * q;
        Acc16 A = {};
        #pragma unroll 1
        for (int ic = 0; ic < 64; ic++) {
            const float* sp = s_in + ic * 132 + (2 * py) * 12 + 2 * px;
            const float4* wq = ((const float4*)s_w) + ic * 9 * 17 + q;
            conv_rows<3, 3, 17>(sp, wq, 12, A);
        }
        #define dst_store(J, V) g_feat[n * 1024 + (oc0 + (J)) * 16 + py * 4 + px] = (V)
        POOL4_STORE(bias)
        #undef dst_store
    }
}

// ---------------------------------------------------------------------------
// GEMM  C[M,N] = A[M,K] @ B[N,K]^T
// ---------------------------------------------------------------------------
template <int BM, int BN, int BK, int TM, int TN, bool MASK, bool SPLITK>
__device__ __forceinline__ void gemm_body(const float* __restrict__ A,
                                          const float* __restrict__ B,
                                          float* __restrict__ C,
                                          int M, int N, int Kd,
                                          const float* __restrict__ dvec) {
    __shared__ float As[BK][BM + 4];
    __shared__ float Bs[BK][BN + 4];
    constexpr int NTr = (BM / TM) * (BN / TN);
    const int tid = threadIdx.x;
    const int tx = tid % (BN / TN);
    const int ty = tid / (BN / TN);
    const int m0 = blockIdx.y * BM;
    const int n0 = blockIdx.x * BN;
    int kBeg = 0, kEnd = Kd;
    if (SPLITK) {
        int kc = Kd / gridDim.z;
        kBeg = blockIdx.z * kc;
        kEnd = kBeg + kc;
        C += (size_t)blockIdx.z * M * N;
    }
    float acc[TM][TN];
    #pragma unroll
    for (int i = 0; i < TM; i++)
        #pragma unroll
        for (int j = 0; j < TN; j++) acc[i][j] = 0.f;

    for (int kk = kBeg; kk < kEnd; kk += BK) {
        for (int i = tid; i < BM * BK; i += NTr) {
            int r = i / BK, c = i % BK;
            float v = A[(m0 + r) * Kd + kk + c];
            if (MASK) v *= (1.0f - dvec[m0 + r]);
            As[c][r] = v;
        }
        for (int i = tid; i < BN * BK; i += NTr) {
            int r = i / BK, c = i % BK;
            Bs[c][r] = B[(n0 + r) * Kd + kk + c];
        }
        __syncthreads();
        #pragma unroll
        for (int k = 0; k < BK; k++) {
            float a[TM], b[TN];
            #pragma unroll
            for (int i = 0; i < TM; i++) a[i] = As[k][ty * TM + i];
            #pragma unroll
            for (int j = 0; j < TN; j++) b[j] = Bs[k][tx * TN + j];
            #pragma unroll
            for (int i = 0; i < TM; i++)
                #pragma unroll
                for (int j = 0; j < TN; j++) acc[i][j] += a[i] * b[j];
        }
        __syncthreads();
    }
    #pragma unroll
    for (int i = 0; i < TM; i++)
        #pragma unroll
        for (int j = 0; j < TN; j++)
            C[(size_t)(m0 + ty * TM + i) * N + n0 + tx * TN + j] = acc[i][j];
}

__global__ void __launch_bounds__(256) gemm_gx_kernel(const float* __restrict__ W_ih) {
    gemm_body<64, 64, 16, 4, 4, false, false>(g_feat, W_ih, g_gx, 1024, 2048, 1024, nullptr);
}

__global__ void __launch_bounds__(256) gemm_hh_kernel(const float* __restrict__ W_hh,
                                                      const float* __restrict__ done, int t) {
    gemm_body<64, 32, 16, 4, 2, true, true>(g_h, W_hh, g_ghh, 64, 2048, 512, done + t * 64);
}

// ---------------------------------------------------------------------------
__device__ __forceinline__ float sigm(float x) { return 1.f / (1.f + expf(-x)); }

__global__ void lstm_update_kernel(const float* __restrict__ b_ih,
                                   const float* __restrict__ b_hh,
                                   const float* __restrict__ done, int t) {
    int idx = blockIdx.x * blockDim.x + threadIdx.x;
    if (idx >= 64 * 512) return;
    int b = idx / 512, j = idx % 512;
    int n = t * 64 + b;
    const float* gx = g_gx + (size_t)n * 2048;
    const float* g1 = g_ghh + (size_t)b * 2048;
    const float* g2 = g_ghh + 64 * 2048 + (size_t)b * 2048;

    float gi = gx[j]        + g1[j]        + g2[j]        + b_ih[j]        + b_hh[j];
    float gf = gx[512 + j]  + g1[512 + j]  + g2[512 + j]  + b_ih[512 + j]  + b_hh[512 + j];
    float gg = gx[1024 + j] + g1[1024 + j] + g2[1024 + j] + b_ih[1024 + j] + b_hh[1024 + j];
    float go = gx[1536 + j] + g1[1536 + j] + g2[1536 + j] + b_ih[1536 + j] + b_hh[1536 + j];

    float m = 1.0f - done[n];
    float c = g_c[idx] * m;
    float cn = sigm(gf) * c + sigm(gi) * tanhf(gg);
    float hn = sigm(go) * tanhf(cn);
    g_c[idx] = cn;
    g_h[idx] = hn;
    g_hidden[(size_t)n * 512 + j] = hn;
}

// ---------------------------------------------------------------------------
__global__ void __launch_bounds__(256) head_kernel(const float* __restrict__ Wa,
                                                   const float* __restrict__ ba,
                                                   const float* __restrict__ Wc,
                                                   const float* __restrict__ bc,
                                                   float* __restrict__ out) {
    int warp = threadIdx.x / 32, lane = threadIdx.x % 32;
    int n = blockIdx.x * 8 + warp;
    float h[16];
    #pragma unroll
    for (int i = 0; i < 16; i++) h[i] = g_hidden[(size_t)n * 512 + i * 32 + lane];
    for (int j = 0; j < 19; j++) {
        const float* w = (j < 18) ? (Wa + j * 512) : Wc;
        float s = 0.f;
        #pragma unroll
        for (int i = 0; i < 16; i++) s += h[i] * w[i * 32 + lane];
        #pragma unroll
        for (int o = 16; o; o >>= 1) s += __shfl_xor_sync(0xffffffffu, s, o);
        if (lane == 0) out[n * 19 + j] = s + ((j < 18) ? ba[j] : bc[0]);
    }
}

__global__ void init_state_kernel(const float* __restrict__ h0, const float* __restrict__ c0) {
    int idx = blockIdx.x * blockDim.x + threadIdx.x;
    if (idx < 64 * 512) { g_h[idx] = h0[idx]; g_c[idx] = c0[idx]; }
}

__global__ void copy_out_kernel(float* __restrict__ out) {
    int idx = blockIdx.x * blockDim.x + threadIdx.x;
    if (idx < 64 * 512) {
        out[19456 + idx] = g_h[idx];
        out[19456 + 32768 + idx] = g_c[idx];
    }
}

// ---------------------------------------------------------------------------
extern "C" void kernel_launch(void* const* d_in, const int* in_sizes, int n_in,
                              void* d_out, int out_size) {
    const float* x    = (const float*)d_in[0];
    const float* done = (const float*)d_in[1];
    const float* h0   = (const float*)d_in[2];
    const float* c0   = (const float*)d_in[3];
    const float* w1   = (const float*)d_in[4];
    const float* b1   = (const float*)d_in[5];
    const float* w2   = (const float*)d_in[6];
    const float* b2   = (const float*)d_in[7];
    const float* w3   = (const float*)d_in[8];
    const float* b3   = (const float*)d_in[9];
    const float* w4   = (const float*)d_in[10];
    const float* b4   = (const float*)d_in[11];
    const float* W_ih = (const float*)d_in[12];
    const float* W_hh = (const float*)d_in[13];
    const float* b_ih = (const float*)d_in[14];
    const float* b_hh = (const float*)d_in[15];
    const float* Wa   = (const float*)d_in[16];
    const float* ba   = (const float*)d_in[17];
    const float* Wc   = (const float*)d_in[18];
    const float* bc   = (const float*)d_in[19];
    float* out = (float*)d_out;

    const int SM1 = (11264 + 3600) * 4;   // 59456
    const int SM2 = (19712 + 28800) * 4;  // 194048
    const int SM3 = (14784 + 34816) * 4;  // 198400
    const int SM4 = (8448 + 39168) * 4;   // 190464
    cudaFuncSetAttribute(conv1_kernel, cudaFuncAttributeMaxDynamicSharedMemorySize, SM1);
    cudaFuncSetAttribute(conv2_kernel, cudaFuncAttributeMaxDynamicSharedMemorySize, SM2);
    cudaFuncSetAttribute(conv3_kernel, cudaFuncAttributeMaxDynamicSharedMemorySize, SM3);
    cudaFuncSetAttribute(conv4_kernel, cudaFuncAttributeMaxDynamicSharedMemorySize, SM4);

    init_state_kernel<<<128, 256>>>(h0, c0);

    conv1_kernel<<<dim3(NSAMP, 3), 320, SM1>>>(x, w1, b1);
    conv2_kernel<<<dim3(NSAMP, 4), 512, SM2>>>(w2, b2);
    conv3_kernel<<<NSAMP, 512, SM3>>>(w3, b3);
    conv4_kernel<<<NSAMP, 256, SM4>>>(w4, b4);

    gemm_gx_kernel<<<dim3(2048 / 64, 1024 / 64, 1), 256>>>(W_ih);

    for (int t = 0; t < 16; t++) {
        gemm_hh_kernel<<<dim3(2048 / 32, 1, 2), 256>>>(W_hh, done, t);
        lstm_update_kernel<<<128, 256>>>(b_ih, b_hh, done, t);
    }

    head_kernel<<<NSAMP / 8, 256>>>(Wa, ba, Wc, bc, out);
    copy_out_kernel<<<128, 256>>>(out);
}